// round 6
// baseline (speedup 1.0000x reference)
#include <cuda_runtime.h>

#define BB 64
#define TT 4096
#define HH 128
#define GG 384   /* 3H */
#define NWORK 84 /* B-worker CTAs; 64 + 84 = 148 = full wave-1 residency */

// Scratch (allocation-free rule: __device__ globals)
__device__ float g_y0[(size_t)BB * TT * HH];    // layer-0 outputs [b][t][k]  128 MiB
__device__ float g_xg1[(size_t)BB * GG * TT];   // layer-1 ih gates [b][g][t] 402 MiB (TRANSPOSED)
__device__ float g_y1[(size_t)BB * TT * HH];    // layer-1 outputs [b][t][k]  128 MiB
__device__ int   g_flagA[BB * 32];              // y0 chunk ready   (producer -> worker)
__device__ int   g_flagB[BB * 32];              // xg1 chunk ready  (worker -> consumer)
__device__ int   g_flagC[BB * 32];              // y1 chunk ready   (consumer -> FC worker)

typedef unsigned long long ull;

static __device__ __forceinline__ ull pk(float a, float b) {
    ull r; asm("mov.b64 %0, {%1, %2};" : "=l"(r) : "f"(a), "f"(b)); return r;
}
static __device__ __forceinline__ void upk(ull v, float& a, float& b) {
    asm("mov.b64 {%0, %1}, %2;" : "=f"(a), "=f"(b) : "l"(v));
}
// Packed fp32x2 FMA / ADD (Blackwell): 2 ops per issue slot
static __device__ __forceinline__ void ffma2(ull& acc, ull a, ull b) {
    asm("fma.rn.f32x2 %0, %1, %2, %0;" : "+l"(acc) : "l"(a), "l"(b));
}
static __device__ __forceinline__ ull add2(ull a, ull b) {
    ull r; asm("add.rn.f32x2 %0, %1, %2;" : "=l"(r) : "l"(a), "l"(b)); return r;
}
static __device__ __forceinline__ float tanha(float x) {     // MUFU tanh
    float y; asm("tanh.approx.f32 %0, %1;" : "=f"(y) : "f"(x)); return y;
}
static __device__ __forceinline__ float sigfast(float x) {   // sigmoid via MUFU tanh
    return fmaf(0.5f, tanha(0.5f * x), 0.5f);
}
static __device__ __forceinline__ int ldacq(const int* p) {
    int v; asm volatile("ld.acquire.gpu.global.b32 %0, [%1];" : "=r"(v) : "l"(p) : "memory");
    return v;
}
static __device__ __forceinline__ void strel(int* p, int v) {
    asm volatile("st.release.gpu.global.b32 [%0], %1;" :: "l"(p), "r"(v) : "memory");
}
static __device__ __forceinline__ void stplain(int* p, int v) {
    asm volatile("st.global.b32 [%0], %1;" :: "l"(p), "r"(v) : "memory");
}

// Load one 128-float weight row into 64 packed register pairs.
static __device__ __forceinline__ void loadw(ull* w, const float* __restrict__ row) {
    const float4* r4 = (const float4*)row;
#pragma unroll
    for (int i = 0; i < 32; i++) {
        float4 v = r4[i];
        w[2 * i]     = pk(v.x, v.y);
        w[2 * i + 1] = pk(v.z, v.w);
    }
}

// dot(w_row[128], hsm[128]) with broadcast LDS.128 + packed FMA, 4 acc chains,
// packed f32x2 tree reduction.
static __device__ __forceinline__ float dot128(const ull* w, const float* hsm) {
    const ulonglong2* h2 = (const ulonglong2*)hsm;
    ull a0 = 0, a1 = 0, a2 = 0, a3 = 0;
#pragma unroll
    for (int k = 0; k < 16; k++) {
        ulonglong2 p = h2[2 * k];
        ulonglong2 q = h2[2 * k + 1];
        ffma2(a0, w[4 * k + 0], p.x);
        ffma2(a1, w[4 * k + 1], p.y);
        ffma2(a2, w[4 * k + 2], q.x);
        ffma2(a3, w[4 * k + 3], q.y);
    }
    ull s = add2(add2(a0, a1), add2(a2, a3));
    float x0, x1; upk(s, x0, x1);
    return x0 + x1;
}

// ===== Mega-kernel: 64 recurrence CTAs (layer0 -> role-switch -> layer1)
//       + 84 worker CTAs (B: xg1 GEMM chunks; then FC epilogue chunks) =====
// Recurrence thread layout: warp=tid>>5, grp=warp/3, role=warp%3 (0=r,1=z,2=n)
// Group g owns hidden units [32g,32g+32); named barrier (g+1) over its 96 threads.
// h double-buffered in SMEM -> one block-wide barrier per timestep.
// All flags are reset by their unique consumer => graph-replay safe, no reset kernel.
__global__ void __launch_bounds__(384, 1)
k_main(const float* __restrict__ data, const float* __restrict__ hidden,
       const float* __restrict__ w_ih0, const float* __restrict__ w_hh0,
       const float* __restrict__ b_ih0, const float* __restrict__ b_hh0,
       const float* __restrict__ w_ih1, const float* __restrict__ w_hh1,
       const float* __restrict__ b_ih1, const float* __restrict__ b_hh1,
       const float* __restrict__ fc_w, const float* __restrict__ fc_b,
       float* __restrict__ out, float* __restrict__ hT) {
    __shared__ __align__(16) float hsm[2][HH];
    __shared__ float s_z[HH];
    __shared__ __align__(8) float2 s_hx[HH];
    __shared__ __align__(16) float xbuf[512];
    __shared__ __align__(16) float ybuf[8 * HH];

    const int tid = threadIdx.x;

    if (blockIdx.x >= BB) {
        // ================== WORKER ==================
        const int wk = blockIdx.x - BB;
        const int lane = tid & 31, warp = tid >> 5;

        // ---- Phase W1: xg1[b][g][t] = w_ih1[g] . y0[b][t] + b_ih1[g] ----
        {
            ull w[64];
            loadw(w, w_ih1 + tid * HH);
            const float bi = b_ih1[tid];

            for (int task = wk; task < BB * 32; task += NWORK) {
                const int c = task >> 6, b = task & 63;   // chunk-major: fresh y0 in L2
                if (tid == 0) {
                    const int* f = g_flagA + b * 32 + c;
                    while (ldacq(f) == 0) __nanosleep(64);
                }
                __syncthreads();
                const float* y0 = g_y0 + ((size_t)b * TT + (size_t)c * 128) * HH;
                float* xo = g_xg1 + (size_t)b * GG * TT + (size_t)tid * TT + c * 128;
                for (int tt = 0; tt < 128; tt += 8) {
                    if (tid < 256) ((float4*)ybuf)[tid] = ((const float4*)(y0 + (size_t)tt * HH))[tid];
                    __syncthreads();
                    float a[8];
#pragma unroll
                    for (int r = 0; r < 8; r++) a[r] = dot128(w, ybuf + r * HH) + bi;
                    float4* o4 = (float4*)(xo + tt);
                    o4[0] = make_float4(a[0], a[1], a[2], a[3]);
                    o4[1] = make_float4(a[4], a[5], a[6], a[7]);
                    __syncthreads();
                }
                if (tid == 0) {
                    stplain(g_flagA + b * 32 + c, 0);     // self-reset for next replay
                    strel(g_flagB + b * 32 + c, 1);
                }
            }
        }

        // ---- Phase W2: FC epilogue  out[b,t] = relu(y1[b,t,:]).fc_w + fc_b ----
        {
            const float4 fw4 = ((const float4*)fc_w)[lane];
            const float fcb = fc_b[0];
            for (int task = wk; task < BB * 32; task += NWORK) {
                const int c = task >> 6, b = task & 63;
                if (tid == 0) {
                    const int* f = g_flagC + b * 32 + c;
                    while (ldacq(f) == 0) __nanosleep(128);
                }
                __syncthreads();
                const float* y1 = g_y1 + ((size_t)b * TT + (size_t)c * 128) * HH;
                float* op = out + (size_t)b * TT + c * 128;
                for (int r = warp; r < 128; r += 12) {
                    float4 yv = ((const float4*)(y1 + (size_t)r * HH))[lane];
                    float p = fmaxf(yv.x, 0.f) * fw4.x + fmaxf(yv.y, 0.f) * fw4.y
                            + fmaxf(yv.z, 0.f) * fw4.z + fmaxf(yv.w, 0.f) * fw4.w;
                    p += __shfl_xor_sync(0xffffffffu, p, 16);
                    p += __shfl_xor_sync(0xffffffffu, p, 8);
                    p += __shfl_xor_sync(0xffffffffu, p, 4);
                    p += __shfl_xor_sync(0xffffffffu, p, 2);
                    p += __shfl_xor_sync(0xffffffffu, p, 1);
                    if (lane == 0) op[r] = p + fcb;
                }
                __syncthreads();
                if (tid == 0) stplain(g_flagC + b * 32 + c, 0);  // self-reset
            }
        }
        return;
    }

    const int warp = tid >> 5, lane = tid & 31;
    const int grp = warp / 3, role = warp - grp * 3;
    const int unit = (grp << 5) | lane;
    const int row = role * HH + unit;
    const int b = blockIdx.x;

    // ================= PHASE 1: layer-0 recurrence (producer) =================
    {
        ull w[64];
        loadw(w, w_hh0 + row * HH);
        const float wi = w_ih0[row], bi = b_ih0[row], bh = b_hh0[row];

        float h_old = hidden[(size_t)b * HH + unit];
        if (role == 0) hsm[0][unit] = h_old;
        __syncthreads();

        const float* xg = data + (size_t)b * TT;
        float* y0 = g_y0 + (size_t)b * TT * HH;
        int* fl = g_flagA + b * 32;

        int cur = 0;
        for (int t = 0; t < TT; t++) {
            if ((t & 511) == 0) {
                if (tid < 128) ((float4*)xbuf)[tid] = ((const float4*)(xg + t))[tid];
                __syncthreads();
            }
            const float x = xbuf[t & 511];
            float acc = dot128(w, hsm[cur]) + bh;
            float xi = fmaf(x, wi, bi);
            float pre = acc + xi;                        // role 0: r_pre
            if (role == 1) s_z[unit] = pre;
            else if (role == 2) s_hx[unit] = make_float2(acc, xi);
            asm volatile("bar.sync %0, 96;" :: "r"(grp + 1) : "memory");
            if (role == 0) {
                float r = sigfast(pre);
                float z = sigfast(s_z[unit]);
                float2 v = s_hx[unit];
                float n = tanha(fmaf(r, v.x, v.y));
                h_old = fmaf(z, h_old - n, n);           // (1-z)n + z h
                hsm[cur ^ 1][unit] = h_old;
                y0[(size_t)t * HH + unit] = h_old;       // ship to B-workers
            }
            __syncthreads();
            // chunk-granular publish: barrier + release store => visible
            if (((t & 127) == 127) && tid == 0) strel(fl + (t >> 7), 1);
            cur ^= 1;
        }
        if (role == 0) hT[(size_t)b * HH + unit] = h_old;
    }

    // ====== PHASE 2 (role-switch): layer-1 recurrence on the same CTA ======
    __syncthreads();
    {
        ull w[64];
        loadw(w, w_hh1 + row * HH);
        const float bh = b_hh1[row];

        float h_old = hidden[(size_t)BB * HH + (size_t)b * HH + unit];
        if (role == 0) hsm[0][unit] = h_old;   // ordered by first chunk's barrier

        // Transposed xg1: this thread's gate-row is a sequential stream over t.
        const float* xgp = g_xg1 + (size_t)b * GG * TT + (size_t)row * TT;
        float* y1 = g_y1 + (size_t)b * TT * HH;

        int cur = 0;
        for (int c = 0; c < 32; c++) {
            if (tid == 0) {
                const int* f = g_flagB + b * 32 + c;
                while (ldacq(f) == 0) __nanosleep(64);
            }
            __syncthreads();
            float xv = xgp[c * 128];
            for (int tt = 0; tt < 128; tt++) {
                const int t = c * 128 + tt;
                // prefetch next x within the chunk (sequential, L1-resident)
                float xnext = (tt < 127) ? xgp[t + 1] : 0.f;
                float acc = dot128(w, hsm[cur]) + bh;
                float pre = acc + xv;                    // role 0: r_pre
                if (role == 1) s_z[unit] = pre;
                else if (role == 2) s_hx[unit] = make_float2(acc, xv);
                asm volatile("bar.sync %0, 96;" :: "r"(grp + 1) : "memory");
                if (role == 0) {
                    float r = sigfast(pre);
                    float z = sigfast(s_z[unit]);
                    float2 v = s_hx[unit];
                    float n = tanha(fmaf(r, v.x, v.y));
                    h_old = fmaf(z, h_old - n, n);
                    hsm[cur ^ 1][unit] = h_old;
                    y1[(size_t)t * HH + unit] = h_old;   // FC done by workers
                }
                __syncthreads();
                xv = xnext;
                cur ^= 1;
            }
            if (tid == 0) {
                stplain(g_flagB + b * 32 + c, 0);        // self-reset
                strel(g_flagC + b * 32 + c, 1);          // y1 chunk -> FC workers
            }
        }
        if (role == 0) hT[(size_t)BB * HH + (size_t)b * HH + unit] = h_old;
    }
}

extern "C" void kernel_launch(void* const* d_in, const int* in_sizes, int n_in,
                              void* d_out, int out_size) {
    const float* data   = (const float*)d_in[0];
    const float* hidden = (const float*)d_in[1];
    const float* w_ih0  = (const float*)d_in[2];
    const float* w_hh0  = (const float*)d_in[3];
    const float* b_ih0  = (const float*)d_in[4];
    const float* b_hh0  = (const float*)d_in[5];
    const float* w_ih1  = (const float*)d_in[6];
    const float* w_hh1  = (const float*)d_in[7];
    const float* b_ih1  = (const float*)d_in[8];
    const float* b_hh1  = (const float*)d_in[9];
    const float* fc_w   = (const float*)d_in[10];
    const float* fc_b   = (const float*)d_in[11];

    float* out = (float*)d_out;
    float* hT  = out + (size_t)BB * TT;   // [2,B,H] final hidden

    k_main<<<BB + NWORK, 384>>>(data, hidden, w_ih0, w_hh0, b_ih0, b_hh0,
                                w_ih1, w_hh1, b_ih1, b_hh1, fc_w, fc_b,
                                out, hT);
}